// round 5
// baseline (speedup 1.0000x reference)
#include <cuda_runtime.h>
#include <cuda_bf16.h>
#include <math_constants.h>
#include <cstdint>

#define M_TOTAL 16384      // 4 * 4096 tokens
#define N_KEYS  4096
#define DHEAD   128
#define HDIM    1024
#define TOPK    8
#define NCAND   12         // approx candidates per half-scan -> exact rescue
#define EPS_F   1e-10f
#define SCALE_F 0.08838834764831845f   // 1/sqrt(128)

#define TM 128             // tokens per CTA
#define TN 128             // keys per tile
#define NTILES (N_KEYS / TN)   // 32

#define QK_STRIDE 272      // bytes per bf16 row (256 data + 16 pad) -> bank rot 4
#define SB_STRIDE 132      // floats per score row

// ---------------- SMEM layout (bytes) ----------------
#define QS_OFF  0                       // 128 x 272            = 34816
#define KS0_OFF 34816                   // 128 x 272            = 34816
#define KS1_OFF 69632                   // 128 x 272            = 34816
#define SB_OFF  104448                  // 128 x 132 f32        = 67584
#define LR_OFF  172032                  // 4096 f32             = 16384
#define SM_TOTAL 188416
// post-loop reuse:
#define MV_OFF QS_OFF                   // float[128][2][NCAND] = 12288
#define MI_OFF (QS_OFF + 12288)         // int  [128][2][NCAND] = 12288
#define CAND_OFF KS0_OFF                // int  [128][NCAND]    = 6144
#define EX_OFF  (KS0_OFF + 6144)        // float[128][NCAND]    = 6144

// Scratch globals
__device__ __nv_bfloat16 g_kbf[(size_t)N_KEYS * DHEAD];   // 1 MB, L2-resident
__device__ float g_logrel[N_KEYS];
__device__ float g_w[M_TOTAL * TOPK];
__device__ int   g_idx[M_TOTAL * TOPK];

// ---------------------------------------------------------------------------
__global__ void prep_kernel(const float* __restrict__ K,
                            const float* __restrict__ rel) {
    int b = blockIdx.x, t = threadIdx.x;
    if (b < (N_KEYS * DHEAD) / 256) {
        int i = b * 256 + t;
        g_kbf[i] = __float2bfloat16(K[i]);
    } else {
        int i = (b - (N_KEYS * DHEAD) / 256) * 256 + t;
        if (i < N_KEYS) g_logrel[i] = logf(rel[i] + EPS_F);
    }
}

// ---------------------------------------------------------------------------
__device__ __forceinline__ uint32_t smem_u32(const void* p) {
    uint32_t a;
    asm("{ .reg .u64 t; cvta.to.shared.u64 t, %1; cvt.u32.u64 %0, t; }"
        : "=r"(a) : "l"(p));
    return a;
}
__device__ __forceinline__ void ldmatrix_x4(uint32_t& r0, uint32_t& r1,
                                            uint32_t& r2, uint32_t& r3,
                                            uint32_t addr) {
    asm volatile("ldmatrix.sync.aligned.m8n8.x4.shared.b16 {%0,%1,%2,%3}, [%4];"
                 : "=r"(r0), "=r"(r1), "=r"(r2), "=r"(r3) : "r"(addr));
}
__device__ __forceinline__ void mma16816(float* c,
    uint32_t a0, uint32_t a1, uint32_t a2, uint32_t a3,
    uint32_t b0, uint32_t b1)
{
    asm volatile(
        "mma.sync.aligned.m16n8k16.row.col.f32.bf16.bf16.f32 "
        "{%0,%1,%2,%3}, {%4,%5,%6,%7}, {%8,%9}, {%0,%1,%2,%3};"
        : "+f"(c[0]), "+f"(c[1]), "+f"(c[2]), "+f"(c[3])
        : "r"(a0), "r"(a1), "r"(a2), "r"(a3), "r"(b0), "r"(b1));
}
__device__ __forceinline__ void cp16(uint32_t dst, const void* src) {
    asm volatile("cp.async.cg.shared.global [%0], [%1], 16;"
                 :: "r"(dst), "l"(src));
}
__device__ __forceinline__ void cp_commit() {
    asm volatile("cp.async.commit_group;");
}
template <int N>
__device__ __forceinline__ void cp_wait() {
    asm volatile("cp.async.wait_group %0;" :: "n"(N));
}

// ---------------------------------------------------------------------------
// Fused: bf16 HMMA scores + online top-12 + exact fp32 rescue + softmax.
// 256 threads = 8 warps; warp w owns token rows [16w, 16w+16).
// ---------------------------------------------------------------------------
__global__ __launch_bounds__(256, 1)
void fused_mma(const float* __restrict__ Q, const float* __restrict__ K,
               float* __restrict__ w_out) {
    extern __shared__ char smem[];
    const uint32_t sb = smem_u32(smem);
    const int tid  = threadIdx.x;
    const int wid  = tid >> 5;
    const int lane = tid & 31;
    const int g    = lane >> 2;      // C-fragment row group
    const int q    = lane & 3;       // C-fragment col group
    const int m0   = blockIdx.x * TM;

    float* Sbm = (float*)(smem + SB_OFF);
    float* lrS = (float*)(smem + LR_OFF);

    // cp.async K tile 0 first (get it in flight)
    {
        const int r = tid >> 4, c16 = tid & 15;   // 8 chunks per thread
        #pragma unroll
        for (int i = 0; i < 8; ++i)
            cp16(sb + KS0_OFF + (r + i * 16) * QK_STRIDE + c16 * 16,
                 g_kbf + (size_t)(r + i * 16) * DHEAD + c16 * 8);
        cp_commit();
    }

    // logrel -> smem
    #pragma unroll
    for (int i = tid; i < N_KEYS; i += 256) lrS[i] = g_logrel[i];

    // Q tile fp32 -> bf16 smem (padded rows)
    #pragma unroll
    for (int i = 0; i < 16; ++i) {
        int idx = tid + i * 256;
        int r = idx >> 5, c4 = idx & 31;
        float4 v = *(const float4*)(Q + (size_t)(m0 + r) * DHEAD + 4 * c4);
        __nv_bfloat162 p0 = __floats2bfloat162_rn(v.x, v.y);
        __nv_bfloat162 p1 = __floats2bfloat162_rn(v.z, v.w);
        *(uint2*)(smem + QS_OFF + r * QK_STRIDE + c4 * 8) =
            make_uint2(*(uint32_t*)&p0, *(uint32_t*)&p1);
    }

    // running top-12 per (token, half-row): strict > keeps first occurrence
    float lv[NCAND];
    int   li[NCAND];
    #pragma unroll
    for (int k = 0; k < NCAND; ++k) { lv[k] = -CUDART_INF_F; li[k] = 0x7fffffff; }
    const int tok = tid >> 1;
    const int hlf = tid & 1;

    // ldmatrix lane-address components (hoisted)
    const int lm  = lane & 7;
    const int s01 = (lane >> 3) & 1;
    const int s23 = (lane >> 4) & 1;
    // A: row += lm + s01*8 ; colbyte = ks*32 + s23*16
    const uint32_t aAddr0 = sb + QS_OFF +
        (uint32_t)(wid * 16 + lm + s01 * 8) * QK_STRIDE + (uint32_t)s23 * 16;
    // B: key = base + lm + s23*8 ; colbyte = ks*32 + s01*16
    const uint32_t bLane = (uint32_t)(lm + s23 * 8) * QK_STRIDE + (uint32_t)s01 * 16;

    for (int t = 0; t < NTILES; ++t) {
        // prefetch K tile t+1 via cp.async into the other buffer
        if (t + 1 < NTILES) {
            const uint32_t dstb = sb + (((t + 1) & 1) ? KS1_OFF : KS0_OFF);
            const int r = tid >> 4, c16 = tid & 15;
            #pragma unroll
            for (int i = 0; i < 8; ++i)
                cp16(dstb + (r + i * 16) * QK_STRIDE + c16 * 16,
                     g_kbf + (size_t)((t + 1) * TN + r + i * 16) * DHEAD + c16 * 8);
            cp_commit();
        }

        // scan scores of tile t-1 (Sb valid since trailing sync of prev iter)
        if (t > 0) {
            const int nb = (t - 1) * TN + hlf * 64;
            const float* srow = Sbm + tok * SB_STRIDE + hlf * 64;
            #pragma unroll
            for (int c4 = 0; c4 < 16; ++c4) {
                float4 sv = *(const float4*)(srow + 4 * c4);
                float vs[4] = {sv.x, sv.y, sv.z, sv.w};
                #pragma unroll
                for (int e = 0; e < 4; ++e) {
                    float v = vs[e];
                    if (v > lv[NCAND - 1]) {
                        lv[NCAND - 1] = v; li[NCAND - 1] = nb + 4 * c4 + e;
                        #pragma unroll
                        for (int s = NCAND - 1; s > 0; --s) {
                            if (lv[s] > lv[s - 1]) {
                                float tv = lv[s]; lv[s] = lv[s-1]; lv[s-1] = tv;
                                int   ti = li[s]; li[s] = li[s-1]; li[s-1] = ti;
                            } else break;
                        }
                    }
                }
            }
        }

        if (t + 1 < NTILES) cp_wait<1>(); else cp_wait<0>();
        __syncthreads();   // K tile t visible to all; scan of t-1 done

        const uint32_t ksBase = sb + ((t & 1) ? KS1_OFF : KS0_OFF) + bLane;
        const int row0 = wid * 16 + g;

        // two half-passes over the 128-key n range (acc = 32 regs)
        #pragma unroll
        for (int hp = 0; hp < 2; ++hp) {
            float acc[8][4];
            #pragma unroll
            for (int b = 0; b < 8; ++b)
                #pragma unroll
                for (int c = 0; c < 4; ++c) acc[b][c] = 0.0f;

            #pragma unroll
            for (int ks = 0; ks < 8; ++ks) {
                uint32_t a0, a1, a2, a3;
                ldmatrix_x4(a0, a1, a2, a3, aAddr0 + ks * 32);
                #pragma unroll
                for (int nb2 = 0; nb2 < 4; ++nb2) {
                    uint32_t b0, b1, b2, b3;
                    ldmatrix_x4(b0, b1, b2, b3,
                        ksBase + (uint32_t)(hp * 64 + nb2 * 16) * QK_STRIDE + ks * 32);
                    mma16816(acc[2 * nb2],     a0, a1, a2, a3, b0, b1);
                    mma16816(acc[2 * nb2 + 1], a0, a1, a2, a3, b2, b3);
                }
            }

            // write biased scores for this half
            #pragma unroll
            for (int b = 0; b < 8; ++b) {
                int col = hp * 64 + b * 8 + 2 * q;
                float lr0 = lrS[t * TN + col];
                float lr1 = lrS[t * TN + col + 1];
                *(float2*)(Sbm + row0 * SB_STRIDE + col) =
                    make_float2(acc[b][0] + lr0, acc[b][1] + lr1);
                *(float2*)(Sbm + (row0 + 8) * SB_STRIDE + col) =
                    make_float2(acc[b][2] + lr0, acc[b][3] + lr1);
            }
        }
        __syncthreads();   // Sb(t) complete; safe to scan next iter / overwrite Ks
    }

    // final scan of tile NTILES-1
    {
        const int nb = (NTILES - 1) * TN + hlf * 64;
        const float* srow = Sbm + tok * SB_STRIDE + hlf * 64;
        #pragma unroll
        for (int c4 = 0; c4 < 16; ++c4) {
            float4 sv = *(const float4*)(srow + 4 * c4);
            float vs[4] = {sv.x, sv.y, sv.z, sv.w};
            #pragma unroll
            for (int e = 0; e < 4; ++e) {
                float v = vs[e];
                if (v > lv[NCAND - 1]) {
                    lv[NCAND - 1] = v; li[NCAND - 1] = nb + 4 * c4 + e;
                    #pragma unroll
                    for (int s = NCAND - 1; s > 0; --s) {
                        if (lv[s] > lv[s - 1]) {
                            float tv = lv[s]; lv[s] = lv[s-1]; lv[s-1] = tv;
                            int   ti = li[s]; li[s] = li[s-1]; li[s-1] = ti;
                        } else break;
                    }
                }
            }
        }
    }
    __syncthreads();   // everyone done with Qs/Ks regions

    // dump per-half candidate lists (reuse Qs region)
    float* mval = (float*)(smem + MV_OFF);
    int*   midx = (int*)(smem + MI_OFF);
    #pragma unroll
    for (int k = 0; k < NCAND; ++k) {
        mval[(tok * 2 + hlf) * NCAND + k] = lv[k];
        midx[(tok * 2 + hlf) * NCAND + k] = li[k];
    }
    __syncthreads();

    // stable merge of two sorted lists -> top-12 candidate indices
    int* candIdx = (int*)(smem + CAND_OFF);
    float* exactS = (float*)(smem + EX_OFF);
    if (tid < TM) {
        const float* va = mval + (tid * 2 + 0) * NCAND;
        const float* vb = mval + (tid * 2 + 1) * NCAND;
        const int*   xa = midx + (tid * 2 + 0) * NCAND;
        const int*   xb = midx + (tid * 2 + 1) * NCAND;
        int ia = 0, ib = 0;
        #pragma unroll
        for (int k = 0; k < NCAND; ++k) {
            float A = va[ia], B = vb[ib];
            bool takeA = (A > B) || (A == B && xa[ia] < xb[ib]);
            candIdx[tid * NCAND + k] = takeA ? xa[ia] : xb[ib];
            if (takeA) ++ia; else ++ib;
        }
    }
    __syncthreads();

    // exact fp32 rescore of 128*12 candidates (6 per thread)
    #pragma unroll
    for (int p = tid; p < TM * NCAND; p += 256) {
        const int tk = p / NCAND;
        const int idx = candIdx[p];
        const float* qrow = Q + (size_t)(m0 + tk) * DHEAD;
        const float* krow = K + (size_t)idx * DHEAD;
        float dot = 0.0f;
        #pragma unroll
        for (int d4 = 0; d4 < DHEAD / 4; ++d4) {
            float4 qv = *(const float4*)(qrow + 4 * d4);
            float4 kv = *(const float4*)(krow + 4 * d4);
            dot = fmaf(qv.x, kv.x, dot);
            dot = fmaf(qv.y, kv.y, dot);
            dot = fmaf(qv.z, kv.z, dot);
            dot = fmaf(qv.w, kv.w, dot);
        }
        exactS[p] = dot + lrS[idx];
    }
    __syncthreads();

    // exact top-8 (desc, index-asc ties), softmax, store
    if (tid < TM) {
        float cv[NCAND]; int ci[NCAND];
        #pragma unroll
        for (int k = 0; k < NCAND; ++k) {
            cv[k] = exactS[tid * NCAND + k];
            ci[k] = candIdx[tid * NCAND + k];
        }
        float fv[TOPK]; int fi[TOPK];
        #pragma unroll
        for (int k = 0; k < TOPK; ++k) {
            int best = 0;
            #pragma unroll
            for (int c = 1; c < NCAND; ++c) {
                bool better = (cv[c] > cv[best]) ||
                              (cv[c] == cv[best] && ci[c] < ci[best]);
                if (better) best = c;
            }
            fv[k] = cv[best]; fi[k] = ci[best];
            cv[best] = -CUDART_INF_F; ci[best] = 0x7fffffff;
        }
        float sc[TOPK], mx = -CUDART_INF_F;
        #pragma unroll
        for (int k = 0; k < TOPK; ++k) {
            sc[k] = (fv[k] - lrS[fi[k]]) * SCALE_F;
            mx = fmaxf(mx, sc[k]);
        }
        float sum = 0.0f;
        #pragma unroll
        for (int k = 0; k < TOPK; ++k) { sc[k] = expf(sc[k] - mx); sum += sc[k]; }
        float inv = 1.0f / sum;
        const int token = m0 + tid;
        #pragma unroll
        for (int k = 0; k < TOPK; ++k) {
            float w = sc[k] * inv;
            w_out[(size_t)token * TOPK + k] = w;
            g_w[token * TOPK + k]   = w;
            g_idx[token * TOPK + k] = fi[k];
        }
    }
}

// ---------------------------------------------------------------------------
// Gather: out[token][h] = sum_k w_k * values[idx_k][h]
// ---------------------------------------------------------------------------
__global__ __launch_bounds__(256)
void gather_kernel(const float* __restrict__ values, float* __restrict__ out) {
    const int token = blockIdx.x;
    const int h = threadIdx.x << 2;

    __shared__ float ws[TOPK];
    __shared__ int   is[TOPK];
    if (threadIdx.x < TOPK) {
        ws[threadIdx.x] = g_w[token * TOPK + threadIdx.x];
        is[threadIdx.x] = g_idx[token * TOPK + threadIdx.x];
    }
    __syncthreads();

    float4 acc = make_float4(0.f, 0.f, 0.f, 0.f);
    #pragma unroll
    for (int k = 0; k < TOPK; ++k) {
        float w = ws[k];
        const float4 v = *(const float4*)(values + (size_t)is[k] * HDIM + h);
        acc.x = fmaf(w, v.x, acc.x);
        acc.y = fmaf(w, v.y, acc.y);
        acc.z = fmaf(w, v.z, acc.z);
        acc.w = fmaf(w, v.w, acc.w);
    }
    *(float4*)(out + (size_t)token * HDIM + h) = acc;
}

// ---------------------------------------------------------------------------
extern "C" void kernel_launch(void* const* d_in, const int* in_sizes, int n_in,
                              void* d_out, int out_size) {
    const float* query = (const float*)d_in[0];   // [4,4096,128]
    const float* keys  = (const float*)d_in[1];   // [4096,128]
    const float* vals  = (const float*)d_in[2];   // [4096,1024]
    const float* rel   = (const float*)d_in[3];   // [4096]

    float* out   = (float*)d_out;                        // [4,4096,1024]
    float* w_out = out + (size_t)M_TOTAL * HDIM;         // [4,4096,8]

    static int configured = -1;
    if (configured < 0) {
        cudaFuncSetAttribute(fused_mma,
                             cudaFuncAttributeMaxDynamicSharedMemorySize, SM_TOTAL);
        configured = 1;
    }

    prep_kernel<<<(N_KEYS * DHEAD) / 256 + (N_KEYS + 255) / 256, 256>>>(keys, rel);
    fused_mma<<<M_TOTAL / TM, 256, SM_TOTAL>>>(query, keys, w_out);
    gather_kernel<<<M_TOTAL, 256>>>(vals, out);
}

// round 6
// speedup vs baseline: 5.4086x; 5.4086x over previous
#include <cuda_runtime.h>
#include <math_constants.h>
#include <cstdint>

#define M_TOTAL 16384      // 4 * 4096 tokens
#define N_KEYS  4096
#define DHEAD   128
#define HDIM    1024
#define TOPK    8
#define EPS_F   1e-10f
#define SCALE_F 0.08838834764831845f   // 1/sqrt(128)

#define TM 128             // tokens per CTA
#define TN 128             // keys per tile
#define NTILES (N_KEYS / TN)   // 32

#define Q_STRIDE 132       // floats per Q/Sb row (16B-aligned, pad vs 128)
#define K_STRIDE 130       // float2 per K d-row (pad vs 128)

// ---------------- SMEM layout (bytes) ----------------
#define QS_OFF 0           // float [128][132] = 67584
#define KS_OFF 67584       // float2[64][130]  = 66560
#define SB_OFF 134144      // float [128][132] = 67584
#define LR_OFF 201728      // float [4096]     = 16384
#define SM_TOTAL 218112
// tail reuse (over Qs region):
#define MV_OFF 0           // float[128][2][TOPK] = 8192
#define MI_OFF 8192        // int  [128][2][TOPK] = 8192

// Scratch globals
__device__ float2 g_kt[(size_t)(DHEAD / 2) * N_KEYS];   // d-major K pairs, 2 MB
__device__ float  g_logrel[N_KEYS];
__device__ float  g_w[M_TOTAL * TOPK];
__device__ int    g_idx[M_TOTAL * TOPK];

// ---------------------------------------------------------------------------
// Prep: K -> d-major float2 pairs (g_kt[d2][key] = {K[key][2d2], K[key][2d2+1]}),
//       logrel = log(rel + eps)
// ---------------------------------------------------------------------------
__global__ void prep_kernel(const float* __restrict__ K,
                            const float* __restrict__ rel) {
    int b = blockIdx.x, t = threadIdx.x;
    if (b < (N_KEYS * DHEAD / 2) / 256) {
        int i = b * 256 + t;
        int key = i & (N_KEYS - 1);
        int d2  = i >> 12;
        g_kt[(size_t)d2 * N_KEYS + key] =
            *(const float2*)(K + (size_t)key * DHEAD + 2 * d2);
    } else {
        int i = (b - (N_KEYS * DHEAD / 2) / 256) * 256 + t;
        if (i < N_KEYS) g_logrel[i] = logf(rel[i] + EPS_F);
    }
}

// ---------------------------------------------------------------------------
__device__ __forceinline__ void fma_x2(unsigned long long& c,
                                       unsigned long long a,
                                       unsigned long long b) {
    asm("fma.rn.f32x2 %0, %1, %2, %0;" : "+l"(c) : "l"(a), "l"(b));
}
__device__ __forceinline__ float hadd_x2(unsigned long long v) {
    float lo, hi;
    asm("mov.b64 {%0, %1}, %2;" : "=f"(lo), "=f"(hi) : "l"(v));
    return lo + hi;
}

// ---------------------------------------------------------------------------
// Fused: exact-fp32 scores via packed f32x2 FMA + online top-8 + softmax.
// 256 threads; tx = tid&15 (key group), ty = tid>>4 (token group).
// Micro-tile: 8 tokens x 4 keys, two 64-key half-passes per 128-key tile.
// ---------------------------------------------------------------------------
__global__ __launch_bounds__(256, 1)
void fused_f32x2(const float* __restrict__ Q, float* __restrict__ w_out) {
    extern __shared__ char smem[];
    float*  Qs  = (float*)(smem + QS_OFF);
    float2* Ks2 = (float2*)(smem + KS_OFF);
    float*  Sb  = (float*)(smem + SB_OFF);
    float*  lrS = (float*)(smem + LR_OFF);

    const int tid = threadIdx.x;
    const int tx  = tid & 15;
    const int ty  = tid >> 4;
    const int m0  = blockIdx.x * TM;

    // logrel -> smem
    #pragma unroll
    for (int i = tid; i < N_KEYS; i += 256) lrS[i] = g_logrel[i];

    // Q tile -> smem (float4, padded rows; 528 B row stride is 16B-aligned)
    #pragma unroll
    for (int i = 0; i < 16; ++i) {
        int idx = tid + i * 256;
        int r = idx >> 5, c4 = idx & 31;
        float4 v = *(const float4*)(Q + (size_t)(m0 + r) * DHEAD + 4 * c4);
        *(float4*)(Qs + r * Q_STRIDE + 4 * c4) = v;
    }

    // running top-8 per (token, key-half): strict > keeps first occurrence
    float lv[TOPK];
    int   li[TOPK];
    #pragma unroll
    for (int k = 0; k < TOPK; ++k) { lv[k] = -CUDART_INF_F; li[k] = 0x7fffffff; }
    const int tok = tid >> 1;
    const int hlf = tid & 1;

    for (int t = 0; t < NTILES; ++t) {
        __syncthreads();   // scan of t-1 done before Ks2 rewrite

        // K tile: g_kt rows d2=0..63, key cols [t*128, t*128+128) (float4 pairs)
        #pragma unroll
        for (int i = 0; i < 16; ++i) {
            int idx = tid + i * 256;
            int d2 = idx >> 6, kc = idx & 63;   // kc = key-pair within tile
            float4 v = *(const float4*)(&g_kt[(size_t)d2 * N_KEYS + t * TN + 2 * kc]);
            *(float4*)(&Ks2[d2 * K_STRIDE + 2 * kc]) = v;
        }
        __syncthreads();

        // two 64-key half passes
        #pragma unroll
        for (int hp = 0; hp < 2; ++hp) {
            unsigned long long acc[8][4];
            #pragma unroll
            for (int i = 0; i < 8; ++i)
                #pragma unroll
                for (int j = 0; j < 4; ++j) acc[i][j] = 0ULL;

            const unsigned long long* Qs8 = (const unsigned long long*)Qs;
            const unsigned long long* Ks8 =
                (const unsigned long long*)(Ks2 + hp * 64 + tx);

            #pragma unroll 4
            for (int d2 = 0; d2 < DHEAD / 2; ++d2) {
                unsigned long long kk[4];
                #pragma unroll
                for (int j = 0; j < 4; ++j)
                    kk[j] = Ks8[d2 * K_STRIDE + 16 * j];
                #pragma unroll
                for (int i = 0; i < 8; ++i) {
                    unsigned long long qq =
                        Qs8[(ty + 16 * i) * (Q_STRIDE / 2) + d2];
                    #pragma unroll
                    for (int j = 0; j < 4; ++j)
                        fma_x2(acc[i][j], qq, kk[j]);
                }
            }

            // biased scores -> Sb
            float lr[4];
            #pragma unroll
            for (int j = 0; j < 4; ++j)
                lr[j] = lrS[t * TN + hp * 64 + 16 * j + tx];
            #pragma unroll
            for (int i = 0; i < 8; ++i) {
                float* row = Sb + (ty + 16 * i) * Q_STRIDE + hp * 64 + tx;
                #pragma unroll
                for (int j = 0; j < 4; ++j)
                    row[16 * j] = hadd_x2(acc[i][j]) + lr[j];
            }
        }
        __syncthreads();   // Sb(t) complete

        // scan: 2 threads per token, 64 keys each (float4 reads)
        const int nb = t * TN + hlf * 64;
        const float* srow = Sb + tok * Q_STRIDE + hlf * 64;
        #pragma unroll
        for (int c4 = 0; c4 < 16; ++c4) {
            float4 sv = *(const float4*)(srow + 4 * c4);
            float vs[4] = {sv.x, sv.y, sv.z, sv.w};
            #pragma unroll
            for (int e = 0; e < 4; ++e) {
                float v = vs[e];
                if (v > lv[TOPK - 1]) {
                    lv[TOPK - 1] = v; li[TOPK - 1] = nb + 4 * c4 + e;
                    #pragma unroll
                    for (int s = TOPK - 1; s > 0; --s) {
                        if (lv[s] > lv[s - 1]) {
                            float tv = lv[s]; lv[s] = lv[s-1]; lv[s-1] = tv;
                            int   ti = li[s]; li[s] = li[s-1]; li[s-1] = ti;
                        } else break;
                    }
                }
            }
        }
    }
    __syncthreads();   // all scans done; Qs region reusable

    // dump per-half candidate lists (reuse Qs region)
    float* mval = (float*)(smem + MV_OFF);
    int*   midx = (int*)(smem + MI_OFF);
    #pragma unroll
    for (int k = 0; k < TOPK; ++k) {
        mval[(tok * 2 + hlf) * TOPK + k] = lv[k];
        midx[(tok * 2 + hlf) * TOPK + k] = li[k];
    }
    __syncthreads();

    // one thread per token: stable merge of two sorted 8-lists, softmax, store
    if (tid < TM) {
        const float* va = mval + (tid * 2 + 0) * TOPK;
        const float* vb = mval + (tid * 2 + 1) * TOPK;
        const int*   xa = midx + (tid * 2 + 0) * TOPK;
        const int*   xb = midx + (tid * 2 + 1) * TOPK;
        float fv[TOPK]; int fi[TOPK];
        int ia = 0, ib = 0;
        #pragma unroll
        for (int k = 0; k < TOPK; ++k) {
            float A = va[ia], B = vb[ib];
            bool takeA = (A > B) || (A == B && xa[ia] < xb[ib]);
            if (takeA) { fv[k] = A; fi[k] = xa[ia]; ++ia; }
            else       { fv[k] = B; fi[k] = xb[ib]; ++ib; }
        }
        float sc[TOPK], mx = -CUDART_INF_F;
        #pragma unroll
        for (int k = 0; k < TOPK; ++k) {
            sc[k] = (fv[k] - lrS[fi[k]]) * SCALE_F;
            mx = fmaxf(mx, sc[k]);
        }
        float sum = 0.0f;
        #pragma unroll
        for (int k = 0; k < TOPK; ++k) { sc[k] = expf(sc[k] - mx); sum += sc[k]; }
        float inv = 1.0f / sum;
        const int token = m0 + tid;
        #pragma unroll
        for (int k = 0; k < TOPK; ++k) {
            float w = sc[k] * inv;
            w_out[(size_t)token * TOPK + k] = w;
            g_w[token * TOPK + k]   = w;
            g_idx[token * TOPK + k] = fi[k];
        }
    }
}

// ---------------------------------------------------------------------------
// Gather: out[token][h] = sum_k w_k * values[idx_k][h]
// ---------------------------------------------------------------------------
__global__ __launch_bounds__(256)
void gather_kernel(const float* __restrict__ values, float* __restrict__ out) {
    const int token = blockIdx.x;
    const int h = threadIdx.x << 2;

    __shared__ float ws[TOPK];
    __shared__ int   is[TOPK];
    if (threadIdx.x < TOPK) {
        ws[threadIdx.x] = g_w[token * TOPK + threadIdx.x];
        is[threadIdx.x] = g_idx[token * TOPK + threadIdx.x];
    }
    __syncthreads();

    float4 acc = make_float4(0.f, 0.f, 0.f, 0.f);
    #pragma unroll
    for (int k = 0; k < TOPK; ++k) {
        float w = ws[k];
        const float4 v = *(const float4*)(values + (size_t)is[k] * HDIM + h);
        acc.x = fmaf(w, v.x, acc.x);
        acc.y = fmaf(w, v.y, acc.y);
        acc.z = fmaf(w, v.z, acc.z);
        acc.w = fmaf(w, v.w, acc.w);
    }
    *(float4*)(out + (size_t)token * HDIM + h) = acc;
}

// ---------------------------------------------------------------------------
extern "C" void kernel_launch(void* const* d_in, const int* in_sizes, int n_in,
                              void* d_out, int out_size) {
    const float* query = (const float*)d_in[0];   // [4,4096,128]
    const float* keys  = (const float*)d_in[1];   // [4096,128]
    const float* vals  = (const float*)d_in[2];   // [4096,1024]
    const float* rel   = (const float*)d_in[3];   // [4096]

    float* out   = (float*)d_out;                        // [4,4096,1024]
    float* w_out = out + (size_t)M_TOTAL * HDIM;         // [4,4096,8]

    cudaFuncSetAttribute(fused_f32x2,
                         cudaFuncAttributeMaxDynamicSharedMemorySize, SM_TOTAL);

    const int ntrans = (N_KEYS * DHEAD / 2) / 256;       // 1024
    prep_kernel<<<ntrans + (N_KEYS + 255) / 256, 256>>>(keys, rel);
    fused_f32x2<<<M_TOTAL / TM, 256, SM_TOTAL>>>(query, w_out);
    gather_kernel<<<M_TOTAL, 256>>>(vals, out);
}